// round 14
// baseline (speedup 1.0000x reference)
#include <cuda_runtime.h>

// DisplacementVectorsASU — gather + per-edge affine transform.
//
// Inputs: frac_coords f32 (100000,3) | edge_indices i32 (2,4M) |
//         symmops f32 (4M,4,4) | cell_translations f32 (4M,3)
// Output: f32 (4M,3)
//
// R14 = R12 main kernel EXACTLY (ct->smem, barrier, then all loads
// front-batched; measured 69.5us twice) + __launch_bounds__(192, 7)
// forcing regs 54->48 => 7 CTAs/SM (42 warps vs 36).
//
// Evidence ledger:
//  - float4 node table, 1 LDG.128/gather (R3) ; default cache policy (R4/R8)
//  - NO cp.async (R7/R8) ; R12 barrier placement beats R13 reorder (measured)
//  - full register front-batching at EPT=2 (R5 > R6, R10)
//  - small smem footprint -> bigger L1 gather carveout (R11)
//  - overhead (pack + graph) is noise-dominated; R3 pack kept

#define NODE_CAP 131072
__device__ float4 g_frac4[NODE_CAP];

__global__ __launch_bounds__(256)
void pack_frac_kernel(const float* __restrict__ frac, int n)
{
    int i = blockIdx.x * blockDim.x + threadIdx.x;
    if (i < n) {
        float4 v;
        v.x = frac[3 * i + 0];
        v.y = frac[3 * i + 1];
        v.z = frac[3 * i + 2];
        v.w = 0.0f;
        g_frac4[i] = v;
    }
}

#define TPB 192
#define EPB 384   // 2 edges per thread

__global__ __launch_bounds__(TPB, 7)
void displacement_kernel(const int*    __restrict__ ei,
                         const float4* __restrict__ sym,   // 4 float4 / edge
                         const float4* __restrict__ ct4,
                         float4*       __restrict__ out4,
                         int M)
{
    __shared__ float s_buf[EPB * 3];   // ct on entry, results on exit (aliased)

    const int tid       = threadIdx.x;
    const int blockBase = blockIdx.x * EPB;

    // ---- cooperative float4 load of cell_translations (coalesced) ----
    {
        const long f4base = (long)blockBase * 3 / 4;    // EPB*3 % 4 == 0
        #pragma unroll
        for (int k = 0; k < 2; k++) {
            int i = tid + k * TPB;
            if (i < EPB * 3 / 4) {
                long idx = f4base + i;
                if (idx * 4 < (long)M * 3)
                    ((float4*)s_buf)[i] = __ldg(ct4 + idx);
            }
        }
    }
    __syncthreads();

    const int e0 = blockBase + tid;
    const int e1 = e0 + TPB;
    const bool v0 = (e0 < M);
    const bool v1 = (e1 < M);

    // ---- front-batch EVERYTHING (R5 pattern): indices, gathers, symmops ----
    int i0a = 0, i0b = 0, i1a = 0, i1b = 0;
    if (v0) { i0a = __ldg(ei + e0); i0b = __ldg(ei + M + e0); }
    if (v1) { i1a = __ldg(ei + e1); i1b = __ldg(ei + M + e1); }

    float4 fin0 = {0,0,0,0}, fo0 = {0,0,0,0};
    float4 fin1 = {0,0,0,0}, fo1 = {0,0,0,0};
    if (v0) { fin0 = __ldg(g_frac4 + i0a); fo0 = __ldg(g_frac4 + i0b); }
    if (v1) { fin1 = __ldg(g_frac4 + i1a); fo1 = __ldg(g_frac4 + i1b); }

    float4 a0 = {0,0,0,0}, a1 = {0,0,0,0}, a2 = {0,0,0,0};
    float4 b0 = {0,0,0,0}, b1 = {0,0,0,0}, b2 = {0,0,0,0};
    if (v0) {
        const long sb = 4L * e0;
        a0 = __ldg(sym + sb + 0);
        a1 = __ldg(sym + sb + 1);
        a2 = __ldg(sym + sb + 2);
    }
    if (v1) {
        const long sb = 4L * e1;
        b0 = __ldg(sym + sb + 0);
        b1 = __ldg(sym + sb + 1);
        b2 = __ldg(sym + sb + 2);
    }

    // ---- compute; each thread reads then overwrites ONLY its own slots ----
    if (v0) {
        float t0 = fmaf(a0.x, fo0.x, fmaf(a0.y, fo0.y, fmaf(a0.z, fo0.z, a0.w)));
        float t1 = fmaf(a1.x, fo0.x, fmaf(a1.y, fo0.y, fmaf(a1.z, fo0.z, a1.w)));
        float t2 = fmaf(a2.x, fo0.x, fmaf(a2.y, fo0.y, fmaf(a2.z, fo0.z, a2.w)));
        const float c0 = s_buf[3 * tid + 0];
        const float c1 = s_buf[3 * tid + 1];
        const float c2 = s_buf[3 * tid + 2];
        s_buf[3 * tid + 0] = fin0.x - (t0 - floorf(t0) + c0);
        s_buf[3 * tid + 1] = fin0.y - (t1 - floorf(t1) + c1);
        s_buf[3 * tid + 2] = fin0.z - (t2 - floorf(t2) + c2);
    }
    if (v1) {
        const int u = tid + TPB;
        float t0 = fmaf(b0.x, fo1.x, fmaf(b0.y, fo1.y, fmaf(b0.z, fo1.z, b0.w)));
        float t1 = fmaf(b1.x, fo1.x, fmaf(b1.y, fo1.y, fmaf(b1.z, fo1.z, b1.w)));
        float t2 = fmaf(b2.x, fo1.x, fmaf(b2.y, fo1.y, fmaf(b2.z, fo1.z, b2.w)));
        const float c0 = s_buf[3 * u + 0];
        const float c1 = s_buf[3 * u + 1];
        const float c2 = s_buf[3 * u + 2];
        s_buf[3 * u + 0] = fin1.x - (t0 - floorf(t0) + c0);
        s_buf[3 * u + 1] = fin1.y - (t1 - floorf(t1) + c1);
        s_buf[3 * u + 2] = fin1.z - (t2 - floorf(t2) + c2);
    }
    __syncthreads();

    // ---- cooperative float4 store of the output (coalesced) ----
    {
        const long f4base = (long)blockBase * 3 / 4;
        #pragma unroll
        for (int k = 0; k < 2; k++) {
            int i = tid + k * TPB;
            if (i < EPB * 3 / 4) {
                long idx = f4base + i;
                if (idx * 4 < (long)M * 3)
                    out4[idx] = ((const float4*)s_buf)[i];
            }
        }
    }
}

extern "C" void kernel_launch(void* const* d_in, const int* in_sizes, int n_in,
                              void* d_out, int out_size)
{
    const float*  frac = (const float*) d_in[0];
    const int*    ei   = (const int*)   d_in[1];
    const float4* sym  = (const float4*)d_in[2];
    const float4* ct4  = (const float4*)d_in[3];
    float4*       out4 = (float4*)      d_out;

    const int n = in_sizes[0] / 3;      // node count
    const int M = in_sizes[1] / 2;      // edge count

    pack_frac_kernel<<<(n + 255) / 256, 256>>>(frac, n);

    const int blocks = (M + EPB - 1) / EPB;
    displacement_kernel<<<blocks, TPB>>>(ei, sym, ct4, out4, M);
}

// round 15
// speedup vs baseline: 1.0908x; 1.0908x over previous
#include <cuda_runtime.h>

// DisplacementVectorsASU — gather + per-edge affine transform.
//
// Inputs: frac_coords f32 (100000,3) | edge_indices i32 (2,4M) |
//         symmops f32 (4M,4,4) | cell_translations f32 (4M,3)
// Output: f32 (4M,3)
//
// R15 = R12 main kernel byte-identical in structure (measured 69.5us twice:
// TPB=192, EPT=2, ct->smem, barrier, ALL loads front-batched, no reg cap)
// + PDL: pack triggers launch_dependents after its stores; main kernel
// launches early and griddepcontrol.waits only before the gathers, hiding
// the pack kernel + launch gap behind its own ct/idx prologue.
//
// Evidence ledger:
//  - float4 node table, 1 LDG.128/gather (R3) ; default cache policy (R4/R8)
//  - NO cp.async (R7/R8); R12 barrier placement (beats R13 reorder)
//  - full register front-batching at EPT=2, NO reg cap (R14: cap -> serialize)
//  - small smem footprint -> bigger L1 gather carveout (R11)
//  - main kernel is at its L1 divergent-replay floor (~69.5us); only the
//    pack/launch overhead is still recoverable.

#define NODE_CAP 131072
__device__ float4 g_frac4[NODE_CAP];

__global__ __launch_bounds__(256)
void pack_frac_kernel(const float* __restrict__ frac, int n)
{
    int i = blockIdx.x * blockDim.x + threadIdx.x;
    if (i < n) {
        float4 v;
        v.x = frac[3 * i + 0];
        v.y = frac[3 * i + 1];
        v.z = frac[3 * i + 2];
        v.w = 0.0f;
        g_frac4[i] = v;
    }
    // Allow the dependent grid to launch; writes above are visible to
    // dependents that execute griddepcontrol.wait.
    asm volatile("griddepcontrol.launch_dependents;" ::: "memory");
}

#define TPB 192
#define EPB 384   // 2 edges per thread

__global__ __launch_bounds__(TPB)
void displacement_kernel(const int*    __restrict__ ei,
                         const float4* __restrict__ sym,   // 4 float4 / edge
                         const float4* __restrict__ ct4,
                         float4*       __restrict__ out4,
                         int M)
{
    __shared__ float s_buf[EPB * 3];   // ct on entry, results on exit (aliased)

    const int tid       = threadIdx.x;
    const int blockBase = blockIdx.x * EPB;

    // ---- cooperative float4 load of cell_translations (coalesced) ----
    // Independent of the packed table: runs while pack finishes.
    {
        const long f4base = (long)blockBase * 3 / 4;    // EPB*3 % 4 == 0
        #pragma unroll
        for (int k = 0; k < 2; k++) {
            int i = tid + k * TPB;
            if (i < EPB * 3 / 4) {
                long idx = f4base + i;
                if (idx * 4 < (long)M * 3)
                    ((float4*)s_buf)[i] = __ldg(ct4 + idx);
            }
        }
    }
    __syncthreads();

    const int e0 = blockBase + tid;
    const int e1 = e0 + TPB;
    const bool v0 = (e0 < M);
    const bool v1 = (e1 < M);

    // ---- front-batch EVERYTHING (R5 pattern): indices, gathers, symmops ----
    int i0a = 0, i0b = 0, i1a = 0, i1b = 0;
    if (v0) { i0a = __ldg(ei + e0); i0b = __ldg(ei + M + e0); }
    if (v1) { i1a = __ldg(ei + e1); i1b = __ldg(ei + M + e1); }

    // Pack results must be visible before the first table gather.
    asm volatile("griddepcontrol.wait;" ::: "memory");

    float4 fin0 = {0,0,0,0}, fo0 = {0,0,0,0};
    float4 fin1 = {0,0,0,0}, fo1 = {0,0,0,0};
    if (v0) { fin0 = __ldg(g_frac4 + i0a); fo0 = __ldg(g_frac4 + i0b); }
    if (v1) { fin1 = __ldg(g_frac4 + i1a); fo1 = __ldg(g_frac4 + i1b); }

    float4 a0 = {0,0,0,0}, a1 = {0,0,0,0}, a2 = {0,0,0,0};
    float4 b0 = {0,0,0,0}, b1 = {0,0,0,0}, b2 = {0,0,0,0};
    if (v0) {
        const long sb = 4L * e0;
        a0 = __ldg(sym + sb + 0);
        a1 = __ldg(sym + sb + 1);
        a2 = __ldg(sym + sb + 2);
    }
    if (v1) {
        const long sb = 4L * e1;
        b0 = __ldg(sym + sb + 0);
        b1 = __ldg(sym + sb + 1);
        b2 = __ldg(sym + sb + 2);
    }

    // ---- compute; each thread reads then overwrites ONLY its own slots ----
    if (v0) {
        float t0 = fmaf(a0.x, fo0.x, fmaf(a0.y, fo0.y, fmaf(a0.z, fo0.z, a0.w)));
        float t1 = fmaf(a1.x, fo0.x, fmaf(a1.y, fo0.y, fmaf(a1.z, fo0.z, a1.w)));
        float t2 = fmaf(a2.x, fo0.x, fmaf(a2.y, fo0.y, fmaf(a2.z, fo0.z, a2.w)));
        const float c0 = s_buf[3 * tid + 0];
        const float c1 = s_buf[3 * tid + 1];
        const float c2 = s_buf[3 * tid + 2];
        s_buf[3 * tid + 0] = fin0.x - (t0 - floorf(t0) + c0);
        s_buf[3 * tid + 1] = fin0.y - (t1 - floorf(t1) + c1);
        s_buf[3 * tid + 2] = fin0.z - (t2 - floorf(t2) + c2);
    }
    if (v1) {
        const int u = tid + TPB;
        float t0 = fmaf(b0.x, fo1.x, fmaf(b0.y, fo1.y, fmaf(b0.z, fo1.z, b0.w)));
        float t1 = fmaf(b1.x, fo1.x, fmaf(b1.y, fo1.y, fmaf(b1.z, fo1.z, b1.w)));
        float t2 = fmaf(b2.x, fo1.x, fmaf(b2.y, fo1.y, fmaf(b2.z, fo1.z, b2.w)));
        const float c0 = s_buf[3 * u + 0];
        const float c1 = s_buf[3 * u + 1];
        const float c2 = s_buf[3 * u + 2];
        s_buf[3 * u + 0] = fin1.x - (t0 - floorf(t0) + c0);
        s_buf[3 * u + 1] = fin1.y - (t1 - floorf(t1) + c1);
        s_buf[3 * u + 2] = fin1.z - (t2 - floorf(t2) + c2);
    }
    __syncthreads();

    // ---- cooperative float4 store of the output (coalesced) ----
    {
        const long f4base = (long)blockBase * 3 / 4;
        #pragma unroll
        for (int k = 0; k < 2; k++) {
            int i = tid + k * TPB;
            if (i < EPB * 3 / 4) {
                long idx = f4base + i;
                if (idx * 4 < (long)M * 3)
                    out4[idx] = ((const float4*)s_buf)[i];
            }
        }
    }
}

extern "C" void kernel_launch(void* const* d_in, const int* in_sizes, int n_in,
                              void* d_out, int out_size)
{
    const float*  frac = (const float*) d_in[0];
    const int*    ei   = (const int*)   d_in[1];
    const float4* sym  = (const float4*)d_in[2];
    const float4* ct4  = (const float4*)d_in[3];
    float4*       out4 = (float4*)      d_out;

    const int n = in_sizes[0] / 3;      // node count
    const int M = in_sizes[1] / 2;      // edge count

    pack_frac_kernel<<<(n + 255) / 256, 256>>>(frac, n);

    // Dependent launch with programmatic stream serialization: the main
    // kernel launches while pack drains; it waits (griddepcontrol.wait)
    // only before touching g_frac4.
    cudaLaunchConfig_t cfg = {};
    cfg.gridDim  = dim3((M + EPB - 1) / EPB, 1, 1);
    cfg.blockDim = dim3(TPB, 1, 1);
    cfg.dynamicSmemBytes = 0;
    cfg.stream = 0;
    cudaLaunchAttribute attr[1];
    attr[0].id = cudaLaunchAttributeProgrammaticStreamSerialization;
    attr[0].val.programmaticStreamSerializationAllowed = 1;
    cfg.attrs = attr;
    cfg.numAttrs = 1;
    cudaLaunchKernelEx(&cfg, displacement_kernel, ei, sym, ct4, out4, M);
}

// round 16
// speedup vs baseline: 1.1172x; 1.0242x over previous
#include <cuda_runtime.h>

// DisplacementVectorsASU — gather + per-edge affine transform.
//
// Inputs: frac_coords f32 (100000,3) | edge_indices i32 (2,4M) |
//         symmops f32 (4M,4,4) | cell_translations f32 (4M,3)
// Output: f32 (4M,3)
//
// R16 = R12 main kernel body byte-identical (measured 69.5us twice) with
// griddepcontrol.wait as the FIRST instruction (R15 showed a mid-kernel
// wait perturbs the load schedule: main 69.5 -> 71.2). PDL still hides the
// pack->main launch gap.
//
// Evidence ledger:
//  - float4 node table, 1 LDG.128/gather (R3) ; default cache policy (R4/R8)
//  - NO cp.async (R7/R8); R12 barrier placement (beats R13/R15 reorders)
//  - full register front-batching at EPT=2, NO reg cap (R14: cap=serialize)
//  - small smem footprint -> bigger L1 gather carveout (R11)
//  - main kernel at its L1 divergent-replay floor (~69.5us)

#define NODE_CAP 131072
__device__ float4 g_frac4[NODE_CAP];

__global__ __launch_bounds__(256)
void pack_frac_kernel(const float* __restrict__ frac, int n)
{
    int i = blockIdx.x * blockDim.x + threadIdx.x;
    if (i < n) {
        float4 v;
        v.x = frac[3 * i + 0];
        v.y = frac[3 * i + 1];
        v.z = frac[3 * i + 2];
        v.w = 0.0f;
        g_frac4[i] = v;
    }
    asm volatile("griddepcontrol.launch_dependents;" ::: "memory");
}

#define TPB 192
#define EPB 384   // 2 edges per thread

__global__ __launch_bounds__(TPB)
void displacement_kernel(const int*    __restrict__ ei,
                         const float4* __restrict__ sym,   // 4 float4 / edge
                         const float4* __restrict__ ct4,
                         float4*       __restrict__ out4,
                         int M)
{
    // Wait FIRST: everything below is the unperturbed R12 body.
    asm volatile("griddepcontrol.wait;" ::: "memory");

    __shared__ float s_buf[EPB * 3];   // ct on entry, results on exit (aliased)

    const int tid       = threadIdx.x;
    const int blockBase = blockIdx.x * EPB;

    // ---- cooperative float4 load of cell_translations (coalesced) ----
    {
        const long f4base = (long)blockBase * 3 / 4;    // EPB*3 % 4 == 0
        #pragma unroll
        for (int k = 0; k < 2; k++) {
            int i = tid + k * TPB;
            if (i < EPB * 3 / 4) {
                long idx = f4base + i;
                if (idx * 4 < (long)M * 3)
                    ((float4*)s_buf)[i] = __ldg(ct4 + idx);
            }
        }
    }
    __syncthreads();

    const int e0 = blockBase + tid;
    const int e1 = e0 + TPB;
    const bool v0 = (e0 < M);
    const bool v1 = (e1 < M);

    // ---- front-batch EVERYTHING (R5 pattern): indices, gathers, symmops ----
    int i0a = 0, i0b = 0, i1a = 0, i1b = 0;
    if (v0) { i0a = __ldg(ei + e0); i0b = __ldg(ei + M + e0); }
    if (v1) { i1a = __ldg(ei + e1); i1b = __ldg(ei + M + e1); }

    float4 fin0 = {0,0,0,0}, fo0 = {0,0,0,0};
    float4 fin1 = {0,0,0,0}, fo1 = {0,0,0,0};
    if (v0) { fin0 = __ldg(g_frac4 + i0a); fo0 = __ldg(g_frac4 + i0b); }
    if (v1) { fin1 = __ldg(g_frac4 + i1a); fo1 = __ldg(g_frac4 + i1b); }

    float4 a0 = {0,0,0,0}, a1 = {0,0,0,0}, a2 = {0,0,0,0};
    float4 b0 = {0,0,0,0}, b1 = {0,0,0,0}, b2 = {0,0,0,0};
    if (v0) {
        const long sb = 4L * e0;
        a0 = __ldg(sym + sb + 0);
        a1 = __ldg(sym + sb + 1);
        a2 = __ldg(sym + sb + 2);
    }
    if (v1) {
        const long sb = 4L * e1;
        b0 = __ldg(sym + sb + 0);
        b1 = __ldg(sym + sb + 1);
        b2 = __ldg(sym + sb + 2);
    }

    // ---- compute; each thread reads then overwrites ONLY its own slots ----
    if (v0) {
        float t0 = fmaf(a0.x, fo0.x, fmaf(a0.y, fo0.y, fmaf(a0.z, fo0.z, a0.w)));
        float t1 = fmaf(a1.x, fo0.x, fmaf(a1.y, fo0.y, fmaf(a1.z, fo0.z, a1.w)));
        float t2 = fmaf(a2.x, fo0.x, fmaf(a2.y, fo0.y, fmaf(a2.z, fo0.z, a2.w)));
        const float c0 = s_buf[3 * tid + 0];
        const float c1 = s_buf[3 * tid + 1];
        const float c2 = s_buf[3 * tid + 2];
        s_buf[3 * tid + 0] = fin0.x - (t0 - floorf(t0) + c0);
        s_buf[3 * tid + 1] = fin0.y - (t1 - floorf(t1) + c1);
        s_buf[3 * tid + 2] = fin0.z - (t2 - floorf(t2) + c2);
    }
    if (v1) {
        const int u = tid + TPB;
        float t0 = fmaf(b0.x, fo1.x, fmaf(b0.y, fo1.y, fmaf(b0.z, fo1.z, b0.w)));
        float t1 = fmaf(b1.x, fo1.x, fmaf(b1.y, fo1.y, fmaf(b1.z, fo1.z, b1.w)));
        float t2 = fmaf(b2.x, fo1.x, fmaf(b2.y, fo1.y, fmaf(b2.z, fo1.z, b2.w)));
        const float c0 = s_buf[3 * u + 0];
        const float c1 = s_buf[3 * u + 1];
        const float c2 = s_buf[3 * u + 2];
        s_buf[3 * u + 0] = fin1.x - (t0 - floorf(t0) + c0);
        s_buf[3 * u + 1] = fin1.y - (t1 - floorf(t1) + c1);
        s_buf[3 * u + 2] = fin1.z - (t2 - floorf(t2) + c2);
    }
    __syncthreads();

    // ---- cooperative float4 store of the output (coalesced) ----
    {
        const long f4base = (long)blockBase * 3 / 4;
        #pragma unroll
        for (int k = 0; k < 2; k++) {
            int i = tid + k * TPB;
            if (i < EPB * 3 / 4) {
                long idx = f4base + i;
                if (idx * 4 < (long)M * 3)
                    out4[idx] = ((const float4*)s_buf)[i];
            }
        }
    }
}

extern "C" void kernel_launch(void* const* d_in, const int* in_sizes, int n_in,
                              void* d_out, int out_size)
{
    const float*  frac = (const float*) d_in[0];
    const int*    ei   = (const int*)   d_in[1];
    const float4* sym  = (const float4*)d_in[2];
    const float4* ct4  = (const float4*)d_in[3];
    float4*       out4 = (float4*)      d_out;

    const int n = in_sizes[0] / 3;      // node count
    const int M = in_sizes[1] / 2;      // edge count

    pack_frac_kernel<<<(n + 255) / 256, 256>>>(frac, n);

    cudaLaunchConfig_t cfg = {};
    cfg.gridDim  = dim3((M + EPB - 1) / EPB, 1, 1);
    cfg.blockDim = dim3(TPB, 1, 1);
    cfg.dynamicSmemBytes = 0;
    cfg.stream = 0;
    cudaLaunchAttribute attr[1];
    attr[0].id = cudaLaunchAttributeProgrammaticStreamSerialization;
    attr[0].val.programmaticStreamSerializationAllowed = 1;
    cfg.attrs = attr;
    cfg.numAttrs = 1;
    cudaLaunchKernelEx(&cfg, displacement_kernel, ei, sym, ct4, out4, M);
}

// round 17
// speedup vs baseline: 1.1196x; 1.0022x over previous
#include <cuda_runtime.h>

// DisplacementVectorsASU — gather + per-edge affine transform.
//
// Inputs: frac_coords f32 (100000,3) | edge_indices i32 (2,4M) |
//         symmops f32 (4M,4,4) | cell_translations f32 (4M,3)
// Output: f32 (4M,3)
//
// R17 = R16 (best total 74.0us) with the griddepcontrol.wait moved from
// kernel entry to just AFTER the ct-epoch __syncthreads(). The ct loads are
// independent of the packed table, so they overlap pack's tail; the wait at
// a barrier boundary cannot perturb the front-batch schedule (loads can't
// be hoisted across bar.sync), unlike R15's mid-batch wait.
//
// Evidence ledger:
//  - float4 node table, 1 LDG.128/gather (R3) ; default cache policy (R4/R8)
//  - NO cp.async (R7/R8); R12 barrier placement (beats R13/R15 reorders)
//  - full register front-batching at EPT=2, NO reg cap (R14: cap=serialize)
//  - small smem footprint -> bigger L1 gather carveout (R11)
//  - PDL hides pack/launch gap (R16: total 75.2 -> 74.0)

#define NODE_CAP 131072
__device__ float4 g_frac4[NODE_CAP];

__global__ __launch_bounds__(256)
void pack_frac_kernel(const float* __restrict__ frac, int n)
{
    int i = blockIdx.x * blockDim.x + threadIdx.x;
    if (i < n) {
        float4 v;
        v.x = frac[3 * i + 0];
        v.y = frac[3 * i + 1];
        v.z = frac[3 * i + 2];
        v.w = 0.0f;
        g_frac4[i] = v;
    }
    asm volatile("griddepcontrol.launch_dependents;" ::: "memory");
}

#define TPB 192
#define EPB 384   // 2 edges per thread

__global__ __launch_bounds__(TPB)
void displacement_kernel(const int*    __restrict__ ei,
                         const float4* __restrict__ sym,   // 4 float4 / edge
                         const float4* __restrict__ ct4,
                         float4*       __restrict__ out4,
                         int M)
{
    __shared__ float s_buf[EPB * 3];   // ct on entry, results on exit (aliased)

    const int tid       = threadIdx.x;
    const int blockBase = blockIdx.x * EPB;

    // ---- ct epoch: independent of the packed table, overlaps pack ----
    {
        const long f4base = (long)blockBase * 3 / 4;    // EPB*3 % 4 == 0
        #pragma unroll
        for (int k = 0; k < 2; k++) {
            int i = tid + k * TPB;
            if (i < EPB * 3 / 4) {
                long idx = f4base + i;
                if (idx * 4 < (long)M * 3)
                    ((float4*)s_buf)[i] = __ldg(ct4 + idx);
            }
        }
    }
    __syncthreads();

    // Table dependency starts below; wait at the barrier boundary so the
    // post-barrier region keeps R12's exact schedule.
    asm volatile("griddepcontrol.wait;" ::: "memory");

    const int e0 = blockBase + tid;
    const int e1 = e0 + TPB;
    const bool v0 = (e0 < M);
    const bool v1 = (e1 < M);

    // ---- front-batch EVERYTHING (R5 pattern): indices, gathers, symmops ----
    int i0a = 0, i0b = 0, i1a = 0, i1b = 0;
    if (v0) { i0a = __ldg(ei + e0); i0b = __ldg(ei + M + e0); }
    if (v1) { i1a = __ldg(ei + e1); i1b = __ldg(ei + M + e1); }

    float4 fin0 = {0,0,0,0}, fo0 = {0,0,0,0};
    float4 fin1 = {0,0,0,0}, fo1 = {0,0,0,0};
    if (v0) { fin0 = __ldg(g_frac4 + i0a); fo0 = __ldg(g_frac4 + i0b); }
    if (v1) { fin1 = __ldg(g_frac4 + i1a); fo1 = __ldg(g_frac4 + i1b); }

    float4 a0 = {0,0,0,0}, a1 = {0,0,0,0}, a2 = {0,0,0,0};
    float4 b0 = {0,0,0,0}, b1 = {0,0,0,0}, b2 = {0,0,0,0};
    if (v0) {
        const long sb = 4L * e0;
        a0 = __ldg(sym + sb + 0);
        a1 = __ldg(sym + sb + 1);
        a2 = __ldg(sym + sb + 2);
    }
    if (v1) {
        const long sb = 4L * e1;
        b0 = __ldg(sym + sb + 0);
        b1 = __ldg(sym + sb + 1);
        b2 = __ldg(sym + sb + 2);
    }

    // ---- compute; each thread reads then overwrites ONLY its own slots ----
    if (v0) {
        float t0 = fmaf(a0.x, fo0.x, fmaf(a0.y, fo0.y, fmaf(a0.z, fo0.z, a0.w)));
        float t1 = fmaf(a1.x, fo0.x, fmaf(a1.y, fo0.y, fmaf(a1.z, fo0.z, a1.w)));
        float t2 = fmaf(a2.x, fo0.x, fmaf(a2.y, fo0.y, fmaf(a2.z, fo0.z, a2.w)));
        const float c0 = s_buf[3 * tid + 0];
        const float c1 = s_buf[3 * tid + 1];
        const float c2 = s_buf[3 * tid + 2];
        s_buf[3 * tid + 0] = fin0.x - (t0 - floorf(t0) + c0);
        s_buf[3 * tid + 1] = fin0.y - (t1 - floorf(t1) + c1);
        s_buf[3 * tid + 2] = fin0.z - (t2 - floorf(t2) + c2);
    }
    if (v1) {
        const int u = tid + TPB;
        float t0 = fmaf(b0.x, fo1.x, fmaf(b0.y, fo1.y, fmaf(b0.z, fo1.z, b0.w)));
        float t1 = fmaf(b1.x, fo1.x, fmaf(b1.y, fo1.y, fmaf(b1.z, fo1.z, b1.w)));
        float t2 = fmaf(b2.x, fo1.x, fmaf(b2.y, fo1.y, fmaf(b2.z, fo1.z, b2.w)));
        const float c0 = s_buf[3 * u + 0];
        const float c1 = s_buf[3 * u + 1];
        const float c2 = s_buf[3 * u + 2];
        s_buf[3 * u + 0] = fin1.x - (t0 - floorf(t0) + c0);
        s_buf[3 * u + 1] = fin1.y - (t1 - floorf(t1) + c1);
        s_buf[3 * u + 2] = fin1.z - (t2 - floorf(t2) + c2);
    }
    __syncthreads();

    // ---- cooperative float4 store of the output (coalesced) ----
    {
        const long f4base = (long)blockBase * 3 / 4;
        #pragma unroll
        for (int k = 0; k < 2; k++) {
            int i = tid + k * TPB;
            if (i < EPB * 3 / 4) {
                long idx = f4base + i;
                if (idx * 4 < (long)M * 3)
                    out4[idx] = ((const float4*)s_buf)[i];
            }
        }
    }
}

extern "C" void kernel_launch(void* const* d_in, const int* in_sizes, int n_in,
                              void* d_out, int out_size)
{
    const float*  frac = (const float*) d_in[0];
    const int*    ei   = (const int*)   d_in[1];
    const float4* sym  = (const float4*)d_in[2];
    const float4* ct4  = (const float4*)d_in[3];
    float4*       out4 = (float4*)      d_out;

    const int n = in_sizes[0] / 3;      // node count
    const int M = in_sizes[1] / 2;      // edge count

    pack_frac_kernel<<<(n + 255) / 256, 256>>>(frac, n);

    cudaLaunchConfig_t cfg = {};
    cfg.gridDim  = dim3((M + EPB - 1) / EPB, 1, 1);
    cfg.blockDim = dim3(TPB, 1, 1);
    cfg.dynamicSmemBytes = 0;
    cfg.stream = 0;
    cudaLaunchAttribute attr[1];
    attr[0].id = cudaLaunchAttributeProgrammaticStreamSerialization;
    attr[0].val.programmaticStreamSerializationAllowed = 1;
    cfg.attrs = attr;
    cfg.numAttrs = 1;
    cudaLaunchKernelEx(&cfg, displacement_kernel, ei, sym, ct4, out4, M);
}